// round 15
// baseline (speedup 1.0000x reference)
#include <cuda_runtime.h>
#include <cuda_fp16.h>
#include <cstdint>

#define NB   8
#define NLQ  2048
#define NLKV 2048
#define ND   128
#define NDV  128

// ---------------------------------------------------------------------------
// device scratch
// ---------------------------------------------------------------------------
__device__ __align__(16) __half g_Qh[NB * NLQ * ND];
__device__ __align__(16) __half g_Kh[NB * NLKV * ND];
__device__ __align__(16) __half g_Vh[NB * NLKV * NDV];
// E = exp(score-4), fp16 fragment groups:
// uint4 index = ((b*32+qb)*16 + t)*1024 + (wr*16 + s*8 + ksv)*32 + lane
__device__ __align__(16) __half g_E[(size_t)NB * NLQ * NLKV];

// ---------------------------------------------------------------------------
// helpers
// ---------------------------------------------------------------------------
__device__ __forceinline__ uint32_t smem_u32(const void* p) {
    uint32_t a;
    asm("{ .reg .u64 t; cvta.to.shared.u64 t, %1; cvt.u32.u64 %0, t; }"
        : "=r"(a) : "l"(p));
    return a;
}
__device__ __forceinline__ void ldsm4(uint32_t (&d)[4], uint32_t addr) {
    asm volatile("ldmatrix.sync.aligned.m8n8.x4.shared.b16 {%0,%1,%2,%3}, [%4];"
        : "=r"(d[0]), "=r"(d[1]), "=r"(d[2]), "=r"(d[3]) : "r"(addr));
}
__device__ __forceinline__ void ldsm4t(uint32_t (&d)[4], uint32_t addr) {
    asm volatile("ldmatrix.sync.aligned.m8n8.x4.trans.shared.b16 {%0,%1,%2,%3}, [%4];"
        : "=r"(d[0]), "=r"(d[1]), "=r"(d[2]), "=r"(d[3]) : "r"(addr));
}
__device__ __forceinline__ void mma16816(float (&c)[4], const uint32_t (&a)[4],
                                         uint32_t b0, uint32_t b1) {
    asm volatile("mma.sync.aligned.m16n8k16.row.col.f32.f16.f16.f32 "
                 "{%0,%1,%2,%3}, {%4,%5,%6,%7}, {%8,%9}, {%0,%1,%2,%3};"
                 : "+f"(c[0]), "+f"(c[1]), "+f"(c[2]), "+f"(c[3])
                 : "r"(a[0]), "r"(a[1]), "r"(a[2]), "r"(a[3]), "r"(b0), "r"(b1));
}
__device__ __forceinline__ void cpasync16(uint32_t s, const void* g) {
    asm volatile("cp.async.cg.shared.global [%0], [%1], 16;" :: "r"(s), "l"(g));
}
#define CP_COMMIT() asm volatile("cp.async.commit_group;")
#define CP_WAIT1()  asm volatile("cp.async.wait_group 1;")
#define CP_WAIT0()  asm volatile("cp.async.wait_group 0;")

// load a ROWSx128 fp16 tile (rows 256B = 16 x 16B chunks), XOR swizzle; 256 thr
template<int ROWS>
__device__ __forceinline__ void cp_tile256(uint32_t sbase,
                                           const __half* __restrict__ g,
                                           int tid) {
    const char* gc = reinterpret_cast<const char*>(g);
#pragma unroll
    for (int it = 0; it < ROWS / 16; it++) {
        int i = tid + it * 256;
        int r = i >> 4, c = i & 15;
        uint32_t soff = (uint32_t)(r * 256 + ((c ^ (r & 7)) << 4));
        cpasync16(sbase + soff, gc + r * 256 + c * 16);
    }
}

// smem layout (64 q-rows per CTA)
constexpr uint32_t OF_Q     = 0;            // 16 KB
constexpr uint32_t OF_B0    = 16384;        // K/V double buffer 2 x 32 KB
constexpr uint32_t OF_STATS = 81920;        // 256 partials + 64 invl
constexpr int SMEM_BYTES    = 83200;

constexpr float EXP_OFF = 4.0f;

// ---------------------------------------------------------------------------
// Kernel 0: convert scale*Q, K, V into fp16
// ---------------------------------------------------------------------------
__global__ void __launch_bounds__(256)
convert_kernel(const float* __restrict__ Q, const float* __restrict__ K,
               const float* __restrict__ V)
{
    const float scale = 0.08838834764831845f;
    int i = blockIdx.x * 256 + threadIdx.x;
    float4 q = reinterpret_cast<const float4*>(Q)[i];
    float4 k = reinterpret_cast<const float4*>(K)[i];
    float4 v = reinterpret_cast<const float4*>(V)[i];
    q.x *= scale; q.y *= scale; q.z *= scale; q.w *= scale;

    float qa[4] = {q.x, q.y, q.z, q.w};
    float ka[4] = {k.x, k.y, k.z, k.w};
    float va[4] = {v.x, v.y, v.z, v.w};
    __half qh[4], kh[4], vh[4];
#pragma unroll
    for (int j = 0; j < 4; j++) {
        qh[j] = __float2half_rn(qa[j]);
        kh[j] = __float2half_rn(ka[j]);
        vh[j] = __float2half_rn(va[j]);
    }
    reinterpret_cast<uint2*>(g_Qh)[i] = *reinterpret_cast<uint2*>(qh);
    reinterpret_cast<uint2*>(g_Kh)[i] = *reinterpret_cast<uint2*>(kh);
    reinterpret_cast<uint2*>(g_Vh)[i] = *reinterpret_cast<uint2*>(vh);
}

// ---------------------------------------------------------------------------
// Fused kernel: 64 q-rows/CTA, 256 thr, 2 CTAs/SM, warp tile 32x32.
// grid (32, 8)
// ---------------------------------------------------------------------------
__global__ void __launch_bounds__(256, 2)
attn_fused(float* __restrict__ W, float* __restrict__ C)
{
    extern __shared__ char sm[];
    const uint32_t sb = smem_u32(sm);
    const int tid = threadIdx.x, l = tid & 31, w = tid >> 5;
    const int wr = w >> 2, wc = w & 3;          // wr: 32-row slab pair; wc: 32-col group
    const int gid = l >> 2, tig = l & 3;
    const int b = blockIdx.y, qb = blockIdx.x, q0 = qb * 64;

    cp_tile256<64>(sb + OF_Q,  g_Qh + (size_t)(b * NLQ + q0) * ND, tid);
    cp_tile256<128>(sb + OF_B0, g_Kh + (size_t)(b * NLKV) * ND, tid);
    CP_COMMIT();

    // A (Q) addressing: two 16-row slabs
    const int rA0 = wr * 32 + (l & 15), rA1 = rA0 + 16;
    const uint32_t aBase0 = sb + OF_Q + rA0 * 256;
    const uint32_t aBase1 = sb + OF_Q + rA1 * 256;
    const int aSw0 = rA0 & 7, aSw1 = rA1 & 7, aC = l >> 4;
    // B (K) addressing
    const int rBo = (l & 7) + ((l >> 4) << 3);
    const int bC  = (l >> 3) & 1;

    uint4* E4 = reinterpret_cast<uint4*>(g_E);
    const uint32_t eCta = (uint32_t)(b * 32 + qb) * 16;
    float ls00 = 0.f, ls01 = 0.f, ls10 = 0.f, ls11 = 0.f;   // [slab][row-half]

    // ------------------------- phase 1: scores -> E -------------------------
    for (int t = 0; t < 16; t++) {
        const uint32_t kb = sb + OF_B0 + (uint32_t)(t & 1) * 32768;
        if (t + 1 < 16) {
            const uint32_t kn = sb + OF_B0 + (uint32_t)((t + 1) & 1) * 32768;
            cp_tile256<128>(kn, g_Kh + (size_t)(b * NLKV + (t + 1) * 128) * ND, tid);
            CP_COMMIT();
            CP_WAIT1();
        } else {
            CP_WAIT0();
        }
        __syncthreads();

        float acc[2][4][4];
#pragma unroll
        for (int s = 0; s < 2; s++)
#pragma unroll
            for (int n = 0; n < 4; n++)
#pragma unroll
                for (int j = 0; j < 4; j++) acc[s][n][j] = 0.f;

#pragma unroll
        for (int ks = 0; ks < 8; ks++) {
            uint32_t bh0[4], bh1[4];
            const int rB0 = wc * 32 + rBo;
            const int rB1 = rB0 + 16;
            ldsm4(bh0, kb + rB0 * 256 + (((2 * ks + bC) ^ (rB0 & 7)) << 4));
            ldsm4(bh1, kb + rB1 * 256 + (((2 * ks + bC) ^ (rB1 & 7)) << 4));
            uint32_t ah0[4], ah1[4];
            ldsm4(ah0, aBase0 + (((2 * ks + aC) ^ aSw0) << 4));
            ldsm4(ah1, aBase1 + (((2 * ks + aC) ^ aSw1) << 4));
            mma16816(acc[0][0], ah0, bh0[0], bh0[1]);
            mma16816(acc[0][1], ah0, bh0[2], bh0[3]);
            mma16816(acc[0][2], ah0, bh1[0], bh1[1]);
            mma16816(acc[0][3], ah0, bh1[2], bh1[3]);
            mma16816(acc[1][0], ah1, bh0[0], bh0[1]);
            mma16816(acc[1][1], ah1, bh0[2], bh0[3]);
            mma16816(acc[1][2], ah1, bh1[0], bh1[1]);
            mma16816(acc[1][3], ah1, bh1[2], bh1[3]);
        }

        // epilogue: exp, row-sum partials, E fragment stores
#pragma unroll
        for (int s = 0; s < 2; s++) {
            float e[4][4];
#pragma unroll
            for (int n = 0; n < 4; n++)
#pragma unroll
                for (int j = 0; j < 4; j++)
                    e[n][j] = __expf(acc[s][n][j] - EXP_OFF);
            float p0 = 0.f, p1 = 0.f;
#pragma unroll
            for (int n = 0; n < 4; n++) {
                p0 += e[n][0] + e[n][1];
                p1 += e[n][2] + e[n][3];
            }
            if (s == 0) { ls00 += p0; ls01 += p1; }
            else        { ls10 += p0; ls11 += p1; }

#pragma unroll
            for (int np = 0; np < 2; np++) {
                const int n0 = 2 * np;
                __half2 j0 = __floats2half2_rn(e[n0][0],     e[n0][1]);
                __half2 j1 = __floats2half2_rn(e[n0][2],     e[n0][3]);
                __half2 j2 = __floats2half2_rn(e[n0 + 1][0], e[n0 + 1][1]);
                __half2 j3 = __floats2half2_rn(e[n0 + 1][2], e[n0 + 1][3]);
                uint4 pk = make_uint4(*reinterpret_cast<uint32_t*>(&j0),
                                      *reinterpret_cast<uint32_t*>(&j1),
                                      *reinterpret_cast<uint32_t*>(&j2),
                                      *reinterpret_cast<uint32_t*>(&j3));
                const int ksv = wc * 2 + np;
                E4[(eCta + t) * 1024 + (uint32_t)(wr * 16 + s * 8 + ksv) * 32 + l] = pk;
            }
        }
        __syncthreads();
    }

    // prefetch V tile 0 while reducing row sums
    cp_tile256<128>(sb + OF_B0, g_Vh + (size_t)(b * NLKV) * NDV, tid);
    CP_COMMIT();

    ls00 += __shfl_xor_sync(0xffffffffu, ls00, 1);
    ls00 += __shfl_xor_sync(0xffffffffu, ls00, 2);
    ls01 += __shfl_xor_sync(0xffffffffu, ls01, 1);
    ls01 += __shfl_xor_sync(0xffffffffu, ls01, 2);
    ls10 += __shfl_xor_sync(0xffffffffu, ls10, 1);
    ls10 += __shfl_xor_sync(0xffffffffu, ls10, 2);
    ls11 += __shfl_xor_sync(0xffffffffu, ls11, 1);
    ls11 += __shfl_xor_sync(0xffffffffu, ls11, 2);
    float* stats = reinterpret_cast<float*>(sm + OF_STATS);  // [wc][64]
    float* sinv  = stats + 256;
    if (tig == 0) {
        stats[wc * 64 + wr * 32 + gid]          = ls00;
        stats[wc * 64 + wr * 32 + gid + 8]      = ls01;
        stats[wc * 64 + wr * 32 + 16 + gid]     = ls10;
        stats[wc * 64 + wr * 32 + 16 + gid + 8] = ls11;
    }
    __syncthreads();
    if (tid < 64)
        sinv[tid] = 1.0f / (stats[tid] + stats[64 + tid]
                            + stats[128 + tid] + stats[192 + tid]);
    __syncthreads();

    const float invl00 = sinv[wr * 32 + gid];
    const float invl01 = sinv[wr * 32 + gid + 8];
    const float invl10 = sinv[wr * 32 + 16 + gid];
    const float invl11 = sinv[wr * 32 + 16 + gid + 8];

    // ------------------------- phase 2: PV + outputs -------------------------
    const int rVo = (l & 7) + (((l >> 3) & 1) << 3);
    const int cVo = l >> 4;

    float accc[2][4][4];
#pragma unroll
    for (int s = 0; s < 2; s++)
#pragma unroll
        for (int n = 0; n < 4; n++)
#pragma unroll
            for (int j = 0; j < 4; j++) accc[s][n][j] = 0.f;

    for (int t = 0; t < 16; t++) {
        const uint32_t vb = sb + OF_B0 + (uint32_t)(t & 1) * 32768;
        if (t + 1 < 16) {
            const uint32_t vn = sb + OF_B0 + (uint32_t)((t + 1) & 1) * 32768;
            cp_tile256<128>(vn, g_Vh + (size_t)(b * NLKV + (t + 1) * 128) * NDV, tid);
            CP_COMMIT();
        }

#pragma unroll
        for (int s = 0; s < 2; s++) {
            uint4 ef[8];
#pragma unroll
            for (int ksv = 0; ksv < 8; ksv++)
                ef[ksv] = E4[(eCta + t) * 1024
                             + (uint32_t)(wr * 16 + s * 8 + ksv) * 32 + l];

            if (s == 0) {
                if (t + 1 < 16) CP_WAIT1(); else CP_WAIT0();
                __syncthreads();
            }

            const float i0 = (s == 0) ? invl00 : invl10;
            const float i1 = (s == 0) ? invl01 : invl11;

#pragma unroll
            for (int ksv = 0; ksv < 8; ksv++) {
                uint32_t a[4] = {ef[ksv].x, ef[ksv].y, ef[ksv].z, ef[ksv].w};
                const int rV = 16 * ksv + rVo;
                const int cV0 = wc * 4 + cVo;
                const int cV1 = cV0 + 2;
                uint32_t bh[4];
                ldsm4t(bh, vb + rV * 256 + ((cV0 ^ (rV & 7)) << 4));
                mma16816(accc[s][0], a, bh[0], bh[1]);
                mma16816(accc[s][1], a, bh[2], bh[3]);
                ldsm4t(bh, vb + rV * 256 + ((cV1 ^ (rV & 7)) << 4));
                mma16816(accc[s][2], a, bh[0], bh[1]);
                mma16816(accc[s][3], a, bh[2], bh[3]);

                // W = E/l: warp wc owns ksv in {2wc, 2wc+1}
                if ((ksv >> 1) == wc) {
                    const int rg = b * NLQ + q0 + wr * 32 + s * 16 + gid;
                    const int cb = t * 128 + ksv * 16 + 2 * tig;
                    float* Wp0 = W + (size_t)rg * NLKV + cb;
                    float* Wp1 = Wp0 + (size_t)8 * NLKV;
                    __half2 h;
                    h = *reinterpret_cast<const __half2*>(&ef[ksv].x);
                    __stcs(reinterpret_cast<float2*>(Wp0),
                           make_float2(__low2float(h) * i0, __high2float(h) * i0));
                    h = *reinterpret_cast<const __half2*>(&ef[ksv].z);
                    __stcs(reinterpret_cast<float2*>(Wp0 + 8),
                           make_float2(__low2float(h) * i0, __high2float(h) * i0));
                    h = *reinterpret_cast<const __half2*>(&ef[ksv].y);
                    __stcs(reinterpret_cast<float2*>(Wp1),
                           make_float2(__low2float(h) * i1, __high2float(h) * i1));
                    h = *reinterpret_cast<const __half2*>(&ef[ksv].w);
                    __stcs(reinterpret_cast<float2*>(Wp1 + 8),
                           make_float2(__low2float(h) * i1, __high2float(h) * i1));
                }
            }
        }
        __syncthreads();
    }

    // C = acc/l
#pragma unroll
    for (int s = 0; s < 2; s++) {
        const float i0 = (s == 0) ? invl00 : invl10;
        const float i1 = (s == 0) ? invl01 : invl11;
        const int rg = b * NLQ + q0 + wr * 32 + s * 16 + gid;
        float* Cp0 = C + (size_t)rg * NDV + wc * 32 + 2 * tig;
        float* Cp1 = Cp0 + (size_t)8 * NDV;
#pragma unroll
        for (int n = 0; n < 4; n++) {
            __stcs(reinterpret_cast<float2*>(Cp0 + 8 * n),
                   make_float2(accc[s][n][0] * i0, accc[s][n][1] * i0));
            __stcs(reinterpret_cast<float2*>(Cp1 + 8 * n),
                   make_float2(accc[s][n][2] * i1, accc[s][n][3] * i1));
        }
    }
}

// ---------------------------------------------------------------------------
extern "C" void kernel_launch(void* const* d_in, const int* in_sizes, int n_in,
                              void* d_out, int out_size)
{
    const float* Q = (const float*)d_in[0];
    const float* K = (const float*)d_in[1];
    const float* V = (const float*)d_in[2];
    float* out = (float*)d_out;

    const size_t W_ELEMS = (size_t)NB * NLQ * NLKV;
    float* Wp = out;
    float* Cp = out + W_ELEMS;

    cudaFuncSetAttribute(attn_fused,
                         cudaFuncAttributeMaxDynamicSharedMemorySize, SMEM_BYTES);

    convert_kernel<<<(NB * NLQ * ND / 4) / 256, 256>>>(Q, K, V);
    attn_fused<<<dim3(NLQ / 64, NB), 256, SMEM_BYTES>>>(Wp, Cp);
}